// round 1
// baseline (speedup 1.0000x reference)
#include <cuda_runtime.h>
#include <math.h>
#include <stdint.h>

// Problem constants (fixed by the reference)
#define NV    50000      // nodes
#define EE    800000     // edges
#define H     128
#define H2    256
#define GG    256
#define KA    144        // extended A width for layer-1 z-GEMM (128 agg_h + 9 attr + deg+1 + 1 + pad)
#define K0W   16         // layer-0 z-GEMM K (a,b, 9 attr, deg+1, 1, pad3)

// ---------------- scratch (static device allocations) ----------------
__device__ int   g_deg[NV];
__device__ int   g_bcnt[NV];
__device__ int   g_rowptr[NV + 1];
__device__ int   g_pos[NV];
__device__ int   g_colidx[EE];
__device__ int   g_tmpscan[NV];
__device__ int   g_blocksum[128];
__device__ int   g_blockoff[128];
__device__ float g_A0[(size_t)NV * K0W];
__device__ float g_Aext[(size_t)NV * KA];
__device__ float g_W0p[K0W * H2];
__device__ float g_W1p[KA * H2];
__device__ float g_z[(size_t)NV * H2];
__device__ float g_h[(size_t)NV * H];
__device__ float g_stats[2 * H2];     // col sums / col sumsq
__device__ float g_scale[H2];
__device__ float g_shift[H2];
__device__ float g_gsum[GG * H];
__device__ float g_gcnt[GG];
__device__ float g_summary[GG * H];
__device__ float g_s2[GG * H];

// ---------------- setup / CSR ----------------
__global__ void k_zero_setup(int n) {
    int total = n * 16;
    for (int idx = blockIdx.x * blockDim.x + threadIdx.x; idx < total;
         idx += gridDim.x * blockDim.x) {
        int v = idx >> 4, j = idx & 15;
        g_Aext[(size_t)v * KA + 128 + j] = 0.f;
        if (j == 0) { g_deg[v] = 0; g_bcnt[v] = 0; }
        if (idx < GG * H) g_gsum[idx] = 0.f;
        if (idx < GG)     g_gcnt[idx] = 0.f;
    }
}

__global__ void k_edge_scatter(const int* __restrict__ src, const int* __restrict__ dst,
                               const float* __restrict__ attr, const int* __restrict__ x_ids,
                               int ecount) {
    int e = blockIdx.x * blockDim.x + threadIdx.x;
    if (e >= ecount) return;
    int s = src[e], d = dst[e];
    atomicAdd(&g_deg[s], 1);
    atomicAdd(&g_bcnt[s], x_ids[d]);
    float* tail = &g_Aext[(size_t)s * KA + 128];
    const float* a = attr + (size_t)e * 9;
#pragma unroll
    for (int j = 0; j < 9; j++) atomicAdd(&tail[j], a[j]);
}

__global__ void k_scan1(int n) {
    __shared__ int s[512];
    int i = blockIdx.x * 512 + threadIdx.x;
    s[threadIdx.x] = (i < n) ? g_deg[i] : 0;
    __syncthreads();
#pragma unroll
    for (int off = 1; off < 512; off <<= 1) {
        int t = 0;
        if ((int)threadIdx.x >= off) t = s[threadIdx.x - off];
        __syncthreads();
        s[threadIdx.x] += t;
        __syncthreads();
    }
    if (i < n) g_tmpscan[i] = s[threadIdx.x];
    if (threadIdx.x == 511) g_blocksum[blockIdx.x] = s[511];
}

__global__ void k_scan2(int nb, int n) {
    if (threadIdx.x == 0 && blockIdx.x == 0) {
        int run = 0;
        for (int b = 0; b < nb; b++) { g_blockoff[b] = run; run += g_blocksum[b]; }
        g_rowptr[n] = run;
    }
}

__global__ void k_scan3(int n) {
    int i = blockIdx.x * blockDim.x + threadIdx.x;
    if (i < n) {
        int r = g_tmpscan[i] - g_deg[i] + g_blockoff[i >> 9];
        g_rowptr[i] = r;
        g_pos[i] = r;
    }
}

__global__ void k_fill(const int* __restrict__ src, const int* __restrict__ dst, int ecount) {
    int e = blockIdx.x * blockDim.x + threadIdx.x;
    if (e >= ecount) return;
    int idx = atomicAdd(&g_pos[src[e]], 1);
    g_colidx[idx] = dst[e];
}

// Finish per-node constants: attr self-loop one-hot(7), deg+1, const-1; build layer-0 A0.
__global__ void k_finalize(const int* __restrict__ x_ids, int n) {
    int v = blockIdx.x * blockDim.x + threadIdx.x;
    if (v >= n) return;
    float* tail = &g_Aext[(size_t)v * KA + 128];
    float t7 = tail[7] + 1.0f;   // self-loop one-hot attr
    tail[7] = t7;
    float dp1 = (float)(g_deg[v] + 1);
    tail[9]  = dp1;   // col 137: coefficient of enc_b@w1_bot
    tail[10] = 1.0f;  // col 138: coefficient of b1
    // cols 139..143 stay zero
    float bfull = (float)(g_bcnt[v] + x_ids[v]);   // # of x_id==1 among neighbors + self
    float* a0 = &g_A0[(size_t)v * K0W];
    a0[0] = dp1 - bfull;
    a0[1] = bfull;
#pragma unroll
    for (int j = 0; j < 9; j++) a0[2 + j] = tail[j];
    a0[11] = dp1;
    a0[12] = 1.f;
    a0[13] = 0.f; a0[14] = 0.f; a0[15] = 0.f;
}

// ---------------- folded weight prep ----------------
// W0p rows: [emb0@w1t, emb1@w1t, (enc_w@w1b) x9, enc_b@w1b, b1, 0,0,0]
__global__ void k_w0prep(const float* __restrict__ node_emb, const float* __restrict__ enc_w,
                         const float* __restrict__ enc_b, const float* __restrict__ w1,
                         const float* __restrict__ b1) {
    int tid = blockIdx.x * blockDim.x + threadIdx.x;
    if (tid < 2 * H2) g_stats[tid] = 0.f;
    if (tid >= K0W * H2) return;
    int row = tid >> 8, col = tid & 255;
    float val = 0.f;
    if (row < 2) {
        for (int k = 0; k < H; k++) val += node_emb[row * H + k] * w1[k * H2 + col];
    } else if (row < 11) {
        int j = row - 2;
        for (int k = 0; k < H; k++) val += enc_w[j * H + k] * w1[(H + k) * H2 + col];
    } else if (row == 11) {
        for (int k = 0; k < H; k++) val += enc_b[k] * w1[(H + k) * H2 + col];
    } else if (row == 12) {
        val = b1[col];
    }
    g_W0p[tid] = val;
}

// W1p rows: [w1_top(128), enc_w@w1b x9, enc_b@w1b, b1, 0 x5]   (layer 1 weights)
__global__ void k_w1prep(const float* __restrict__ enc_w, const float* __restrict__ enc_b,
                         const float* __restrict__ w1, const float* __restrict__ b1) {
    int tid = blockIdx.x * blockDim.x + threadIdx.x;
    if (tid < 2 * H2) g_stats[tid] = 0.f;
    if (tid >= KA * H2) return;
    int row = tid >> 8, col = tid & 255;
    const float* w1L = w1 + H2 * H2;
    float val = 0.f;
    if (row < 128) {
        val = w1L[row * H2 + col];
    } else if (row < 137) {
        int j = row - 128;
        for (int k = 0; k < H; k++) val += enc_w[9 * H + j * H + k] * w1L[(H + k) * H2 + col];
    } else if (row == 137) {
        for (int k = 0; k < H; k++) val += enc_b[H + k] * w1L[(H + k) * H2 + col];
    } else if (row == 138) {
        val = b1[H2 + col];
    }
    g_W1p[tid] = val;
}

// ---------------- register-tiled SGEMM 128x128x8, 256 threads, 8x8/thread ----------------
// TRANS_A: A element -> max(0, a*g_scale[k]+g_shift[k])  (fused BN+ReLU read of z)
// HAS_EPI: C += bias[col]; optional ReLU
template <bool TRANS_A, bool HAS_EPI>
__global__ void __launch_bounds__(256, 2)
sgemm128(const float* __restrict__ A, int lda,
         const float* __restrict__ B, int ldb,
         float* __restrict__ C, int ldc,
         int M, int K,
         const float* __restrict__ bias, int do_relu) {
    __shared__ float As[8][128];
    __shared__ float Bs[8][128];
    int tid = threadIdx.x;
    int tx = tid & 15, ty = tid >> 4;
    int m0 = blockIdx.x * 128, n0 = blockIdx.y * 128;

    float acc[8][8];
#pragma unroll
    for (int i = 0; i < 8; i++)
#pragma unroll
        for (int j = 0; j < 8; j++) acc[i][j] = 0.f;

    int arow = tid >> 1;
    int acol = (tid & 1) << 2;
    int brow = tid >> 5;
    int bcol = (tid & 31) << 2;

    for (int k0 = 0; k0 < K; k0 += 8) {
        int gm = m0 + arow;
        int gk = k0 + acol;
        float4 av = make_float4(0.f, 0.f, 0.f, 0.f);
        if (gm < M) av = *(const float4*)(A + (size_t)gm * lda + gk);
        if (TRANS_A) {
            av.x = fmaxf(fmaf(av.x, g_scale[gk + 0], g_shift[gk + 0]), 0.f);
            av.y = fmaxf(fmaf(av.y, g_scale[gk + 1], g_shift[gk + 1]), 0.f);
            av.z = fmaxf(fmaf(av.z, g_scale[gk + 2], g_shift[gk + 2]), 0.f);
            av.w = fmaxf(fmaf(av.w, g_scale[gk + 3], g_shift[gk + 3]), 0.f);
        }
        As[acol + 0][arow] = av.x;
        As[acol + 1][arow] = av.y;
        As[acol + 2][arow] = av.z;
        As[acol + 3][arow] = av.w;

        float4 bv = *(const float4*)(B + (size_t)(k0 + brow) * ldb + n0 + bcol);
        *(float4*)&Bs[brow][bcol] = bv;
        __syncthreads();

#pragma unroll
        for (int kk = 0; kk < 8; kk++) {
            float4 a0 = *(float4*)&As[kk][ty * 8];
            float4 a1 = *(float4*)&As[kk][ty * 8 + 4];
            float4 b0 = *(float4*)&Bs[kk][tx * 8];
            float4 b1 = *(float4*)&Bs[kk][tx * 8 + 4];
            float a[8] = {a0.x, a0.y, a0.z, a0.w, a1.x, a1.y, a1.z, a1.w};
            float b[8] = {b0.x, b0.y, b0.z, b0.w, b1.x, b1.y, b1.z, b1.w};
#pragma unroll
            for (int i = 0; i < 8; i++)
#pragma unroll
                for (int j = 0; j < 8; j++) acc[i][j] = fmaf(a[i], b[j], acc[i][j]);
        }
        __syncthreads();
    }

#pragma unroll
    for (int i = 0; i < 8; i++) {
        int gm = m0 + ty * 8 + i;
        if (gm >= M) continue;
        float* crow = C + (size_t)gm * ldc + n0 + tx * 8;
#pragma unroll
        for (int j0 = 0; j0 < 8; j0 += 4) {
            float4 v = make_float4(acc[i][j0], acc[i][j0 + 1], acc[i][j0 + 2], acc[i][j0 + 3]);
            if (HAS_EPI) {
                int col = n0 + tx * 8 + j0;
                v.x += bias[col + 0]; v.y += bias[col + 1];
                v.z += bias[col + 2]; v.w += bias[col + 3];
                if (do_relu) {
                    v.x = fmaxf(v.x, 0.f); v.y = fmaxf(v.y, 0.f);
                    v.z = fmaxf(v.z, 0.f); v.w = fmaxf(v.w, 0.f);
                }
            }
            *(float4*)(crow + j0) = v;
        }
    }
}

// ---------------- BN stats / finalize ----------------
__global__ void k_colstats(int M) {
    int c = threadIdx.x;                     // 256 cols
    int r0 = blockIdx.x * 256;
    int rend = min(256, M - r0);
    float s = 0.f, s2 = 0.f;
    const float* zp = g_z + (size_t)r0 * H2 + c;
    for (int r = 0; r < rend; r++) {
        float v = zp[(size_t)r * H2];
        s += v; s2 += v * v;
    }
    atomicAdd(&g_stats[c], s);
    atomicAdd(&g_stats[H2 + c], s2);
}

__global__ void k_bnfinal(const float* __restrict__ bn_g, const float* __restrict__ bn_b,
                          int layer, int M) {
    int c = threadIdx.x;
    float inv = 1.f / (float)M;
    float mu = g_stats[c] * inv;
    float var = g_stats[H2 + c] * inv - mu * mu;
    float rs = rsqrtf(var + 1e-5f);
    float sc = bn_g[layer * H2 + c] * rs;
    g_scale[c] = sc;
    g_shift[c] = bn_b[layer * H2 + c] - mu * sc;
}

// ---------------- SpMM: Aext[:,0:128] = (A + I) @ h,  one warp per node ----------------
__global__ void k_spmm(int n) {
    int wid = (blockIdx.x * blockDim.x + threadIdx.x) >> 5;
    int lane = threadIdx.x & 31;
    if (wid >= n) return;
    const float4* h4 = (const float4*)g_h;
    float4 acc = h4[(size_t)wid * 32 + lane];   // self loop
    int e0 = g_rowptr[wid], e1 = g_rowptr[wid + 1];
    for (int e = e0; e < e1; e++) {
        int c = g_colidx[e];
        float4 hv = h4[(size_t)c * 32 + lane];
        acc.x += hv.x; acc.y += hv.y; acc.z += hv.z; acc.w += hv.w;
    }
    ((float4*)(g_Aext + (size_t)wid * KA))[lane] = acc;
}

// ---------------- InfoMax head ----------------
__global__ void k_gsum(const int* __restrict__ batch, int n) {
    int wid = (blockIdx.x * blockDim.x + threadIdx.x) >> 5;
    int lane = threadIdx.x & 31;
    if (wid >= n) return;
    int g = batch[wid];
    const float4* h4 = (const float4*)g_h;
    float4 hv = h4[(size_t)wid * 32 + lane];
    float* p = g_gsum + (size_t)g * H + lane * 4;
    atomicAdd(p + 0, hv.x); atomicAdd(p + 1, hv.y);
    atomicAdd(p + 2, hv.z); atomicAdd(p + 3, hv.w);
    if (lane == 0) atomicAdd(&g_gcnt[g], 1.f);
}

__global__ void k_summary() {
    int tid = blockIdx.x * blockDim.x + threadIdx.x;
    if (tid >= GG * H) return;
    int g = tid >> 7;
    float cnt = fmaxf(g_gcnt[g], 1.f);
    float s = g_gsum[tid] / cnt;
    g_summary[tid] = 1.f / (1.f + expf(-s));
}

__global__ void k_s2(const float* __restrict__ disc_w) {
    __shared__ float srow[H];
    int g = blockIdx.x;
    int c = threadIdx.x;
    srow[c] = g_summary[g * H + c];
    __syncthreads();
    float acc = 0.f;
    for (int k = 0; k < H; k++) acc = fmaf(srow[k], disc_w[k * H + c], acc);
    g_s2[g * H + c] = acc;
}

__global__ void k_out(const int* __restrict__ batch, float* __restrict__ out, int n) {
    int wid = (blockIdx.x * blockDim.x + threadIdx.x) >> 5;
    int lane = threadIdx.x & 31;
    if (wid >= n) return;
    int g = batch[wid];
    int g2 = (g + 1) % GG;
    const float4* h4 = (const float4*)g_h;
    const float4* s4 = (const float4*)g_s2;
    float4 hv = h4[(size_t)wid * 32 + lane];
    float4 av = s4[(size_t)g * 32 + lane];
    float4 bv = s4[(size_t)g2 * 32 + lane];
    float p = hv.x * av.x + hv.y * av.y + hv.z * av.z + hv.w * av.w;
    float q = hv.x * bv.x + hv.y * bv.y + hv.z * bv.z + hv.w * bv.w;
#pragma unroll
    for (int off = 16; off > 0; off >>= 1) {
        p += __shfl_xor_sync(0xffffffff, p, off);
        q += __shfl_xor_sync(0xffffffff, q, off);
    }
    if (lane == 0) { out[wid] = p; out[n + wid] = q; }
}

// ---------------- host ----------------
extern "C" void kernel_launch(void* const* d_in, const int* in_sizes, int n_in,
                              void* d_out, int out_size) {
    const int*   x_ids     = (const int*)d_in[0];
    const int*   ei        = (const int*)d_in[1];
    const int*   batch     = (const int*)d_in[2];
    const float* edge_attr = (const float*)d_in[3];
    const float* node_emb  = (const float*)d_in[4];
    const float* enc_w     = (const float*)d_in[5];
    const float* enc_b     = (const float*)d_in[6];
    const float* w1        = (const float*)d_in[7];
    const float* b1        = (const float*)d_in[8];
    const float* bn_g      = (const float*)d_in[9];
    const float* bn_b      = (const float*)d_in[10];
    const float* w2        = (const float*)d_in[11];
    const float* b2        = (const float*)d_in[12];
    const float* disc_w    = (const float*)d_in[13];
    float* out = (float*)d_out;

    int n  = in_sizes[0];
    int ec = in_sizes[1] / 2;
    const int* src = ei;
    const int* dst = ei + ec;

    float *p_A0, *p_Aext, *p_z, *p_h, *p_W0p, *p_W1p;
    cudaGetSymbolAddress((void**)&p_A0,   g_A0);
    cudaGetSymbolAddress((void**)&p_Aext, g_Aext);
    cudaGetSymbolAddress((void**)&p_z,    g_z);
    cudaGetSymbolAddress((void**)&p_h,    g_h);
    cudaGetSymbolAddress((void**)&p_W0p,  g_W0p);
    cudaGetSymbolAddress((void**)&p_W1p,  g_W1p);

    int eb   = (ec + 255) / 256;
    int nb   = (n + 255) / 256;
    int nb512 = (n + 511) / 512;
    int mb   = (n + 127) / 128;
    int warpsB = (n * 32 + 255) / 256;

    // --- phase A: graph structure + layer-independent features ---
    k_zero_setup<<<(n * 16 + 255) / 256, 256>>>(n);
    k_edge_scatter<<<eb, 256>>>(src, dst, edge_attr, x_ids, ec);
    k_scan1<<<nb512, 512>>>(n);
    k_scan2<<<1, 1>>>(nb512, n);
    k_scan3<<<nb, 256>>>(n);
    k_fill<<<eb, 256>>>(src, dst, ec);
    k_finalize<<<nb, 256>>>(x_ids, n);

    // --- layer 0 ---
    k_w0prep<<<16, 256>>>(node_emb, enc_w, enc_b, w1, b1);
    sgemm128<false, false><<<dim3(mb, 2), 256>>>(p_A0, K0W, p_W0p, H2, p_z, H2, n, K0W,
                                                 nullptr, 0);
    k_colstats<<<(n + 255) / 256, 256>>>(n);
    k_bnfinal<<<1, 256>>>(bn_g, bn_b, 0, n);
    sgemm128<true, true><<<dim3(mb, 1), 256>>>(p_z, H2, w2, H, p_h, H, n, H2,
                                               b2, 1);

    // --- layer 1 ---
    k_w1prep<<<144, 256>>>(enc_w, enc_b, w1, b1);
    k_spmm<<<warpsB, 256>>>(n);
    sgemm128<false, false><<<dim3(mb, 2), 256>>>(p_Aext, KA, p_W1p, H2, p_z, H2, n, KA,
                                                 nullptr, 0);
    k_colstats<<<(n + 255) / 256, 256>>>(n);
    k_bnfinal<<<1, 256>>>(bn_g, bn_b, 1, n);
    sgemm128<true, true><<<dim3(mb, 1), 256>>>(p_z, H2, w2 + (size_t)H2 * H, H, p_h, H, n, H2,
                                               b2 + H, 0);

    // --- head ---
    k_gsum<<<warpsB, 256>>>(batch, n);
    k_summary<<<(GG * H + 255) / 256, 256>>>();
    k_s2<<<GG, H>>>(disc_w);
    k_out<<<warpsB, 256>>>(batch, out, n);
}

// round 3
// speedup vs baseline: 1.5979x; 1.5979x over previous
#include <cuda_runtime.h>
#include <cuda_bf16.h>
#include <math.h>
#include <stdint.h>

// Problem constants (fixed by the reference)
#define NV    50000
#define EE    800000
#define H     128
#define H2    256
#define GG    256
#define KA    144        // layer-1 A width (128 agg_h + 9 attr + deg+1 + 1 + 5 pad)
#define K0W   16         // layer-0 A width

// ---------------- scratch ----------------
__device__ int   g_deg[NV];
__device__ int   g_bcnt[NV];
__device__ int   g_rowptr[NV + 1];
__device__ int   g_pos[NV];
__device__ int   g_colidx[EE];
__device__ int   g_tmpscan[NV];
__device__ int   g_blocksum[128];
__device__ int   g_blockoff[128];
__device__ float g_A0[(size_t)NV * K0W];
__device__ float g_Aext[(size_t)NV * KA];
__device__ float g_W0p[K0W * H2];
__device__ float g_W1p[KA * H2];
__device__ float g_z[(size_t)NV * H2];
__device__ float g_h[(size_t)NV * H];
__device__ float g_stats[2 * H2];
__device__ float g_s2[GG * H];

// ---------------- setup / CSR ----------------
__global__ void k_zero_setup(int n) {
    int total = n * 16;
    for (int idx = blockIdx.x * blockDim.x + threadIdx.x; idx < total;
         idx += gridDim.x * blockDim.x) {
        int v = idx >> 4, j = idx & 15;
        g_Aext[(size_t)v * KA + 128 + j] = 0.f;
        if (j == 0) { g_deg[v] = 0; g_bcnt[v] = 0; }
    }
}

__global__ void k_edge_scatter(const int* __restrict__ src, const int* __restrict__ dst,
                               const float* __restrict__ attr, const int* __restrict__ x_ids,
                               int ecount) {
    int e = blockIdx.x * blockDim.x + threadIdx.x;
    if (e >= ecount) return;
    int s = src[e], d = dst[e];
    atomicAdd(&g_deg[s], 1);
    atomicAdd(&g_bcnt[s], x_ids[d]);
    float* tail = &g_Aext[(size_t)s * KA + 128];
    const float* a = attr + (size_t)e * 9;
#pragma unroll
    for (int j = 0; j < 9; j++) atomicAdd(&tail[j], a[j]);
}

__global__ void k_scan1(int n) {
    __shared__ int s[512];
    int i = blockIdx.x * 512 + threadIdx.x;
    s[threadIdx.x] = (i < n) ? g_deg[i] : 0;
    __syncthreads();
#pragma unroll
    for (int off = 1; off < 512; off <<= 1) {
        int t = 0;
        if ((int)threadIdx.x >= off) t = s[threadIdx.x - off];
        __syncthreads();
        s[threadIdx.x] += t;
        __syncthreads();
    }
    if (i < n) g_tmpscan[i] = s[threadIdx.x];
    if (threadIdx.x == 511) g_blocksum[blockIdx.x] = s[511];
}

__global__ void k_scan2(int nb, int n) {
    __shared__ int sh[128];
    int t = threadIdx.x;
    int v = (t < nb) ? g_blocksum[t] : 0;
    sh[t] = v;
    __syncthreads();
#pragma unroll
    for (int off = 1; off < 128; off <<= 1) {
        int x = (t >= off) ? sh[t - off] : 0;
        __syncthreads();
        sh[t] += x;
        __syncthreads();
    }
    if (t < nb) g_blockoff[t] = sh[t] - v;
    if (t == 127) g_rowptr[n] = sh[127];
}

__global__ void k_scan3(int n) {
    int i = blockIdx.x * blockDim.x + threadIdx.x;
    if (i < n) {
        int r = g_tmpscan[i] - g_deg[i] + g_blockoff[i >> 9];
        g_rowptr[i] = r;
        g_pos[i] = r;
    }
}

__global__ void k_fill(const int* __restrict__ src, const int* __restrict__ dst, int ecount) {
    int e = blockIdx.x * blockDim.x + threadIdx.x;
    if (e >= ecount) return;
    int idx = atomicAdd(&g_pos[src[e]], 1);
    g_colidx[idx] = dst[e];
}

__global__ void k_finalize(const int* __restrict__ x_ids, int n) {
    int v = blockIdx.x * blockDim.x + threadIdx.x;
    if (v >= n) return;
    float* tail = &g_Aext[(size_t)v * KA + 128];
    float t7 = tail[7] + 1.0f;
    tail[7] = t7;
    float dp1 = (float)(g_deg[v] + 1);
    tail[9]  = dp1;
    tail[10] = 1.0f;
    float bfull = (float)(g_bcnt[v] + x_ids[v]);
    float* a0 = &g_A0[(size_t)v * K0W];
    a0[0] = dp1 - bfull;
    a0[1] = bfull;
#pragma unroll
    for (int j = 0; j < 9; j++) a0[2 + j] = tail[j];
    a0[11] = dp1;
    a0[12] = 1.f;
    a0[13] = 0.f; a0[14] = 0.f; a0[15] = 0.f;
}

// ---------------- folded weight prep (also zeroes g_stats) ----------------
__global__ void k_w0prep(const float* __restrict__ node_emb, const float* __restrict__ enc_w,
                         const float* __restrict__ enc_b, const float* __restrict__ w1,
                         const float* __restrict__ b1) {
    int tid = blockIdx.x * blockDim.x + threadIdx.x;
    if (tid < 2 * H2) g_stats[tid] = 0.f;
    if (tid >= K0W * H2) return;
    int row = tid >> 8, col = tid & 255;
    float val = 0.f;
    if (row < 2) {
        for (int k = 0; k < H; k++) val += node_emb[row * H + k] * w1[k * H2 + col];
    } else if (row < 11) {
        int j = row - 2;
        for (int k = 0; k < H; k++) val += enc_w[j * H + k] * w1[(H + k) * H2 + col];
    } else if (row == 11) {
        for (int k = 0; k < H; k++) val += enc_b[k] * w1[(H + k) * H2 + col];
    } else if (row == 12) {
        val = b1[col];
    }
    g_W0p[tid] = val;
}

__global__ void k_w1prep(const float* __restrict__ enc_w, const float* __restrict__ enc_b,
                         const float* __restrict__ w1, const float* __restrict__ b1) {
    int tid = blockIdx.x * blockDim.x + threadIdx.x;
    if (tid < 2 * H2) g_stats[tid] = 0.f;
    if (tid >= KA * H2) return;
    int row = tid >> 8, col = tid & 255;
    const float* w1L = w1 + H2 * H2;
    float val = 0.f;
    if (row < 128) {
        val = w1L[row * H2 + col];
    } else if (row < 137) {
        int j = row - 128;
        for (int k = 0; k < H; k++) val += enc_w[9 * H + j * H + k] * w1L[(H + k) * H2 + col];
    } else if (row == 137) {
        for (int k = 0; k < H; k++) val += enc_b[H + k] * w1L[(H + k) * H2 + col];
    } else if (row == 138) {
        val = b1[H2 + col];
    }
    g_W1p[tid] = val;
}

// ---------------- precision-compensated bf16 GEMM 128x128x16, 8 warps ----------------
// Split x = hi + lo (two bf16); D = Ah*Bh + Ah*Bl + Al*Bh (fp32 accum).
__device__ __forceinline__ void splitpack(float x, float y, uint32_t& hi, uint32_t& lo) {
    __nv_bfloat16 hx = __float2bfloat16_rn(x);
    __nv_bfloat16 hy = __float2bfloat16_rn(y);
    __nv_bfloat16 lx = __float2bfloat16_rn(x - __bfloat162float(hx));
    __nv_bfloat16 ly = __float2bfloat16_rn(y - __bfloat162float(hy));
    hi = ((uint32_t)__bfloat16_as_ushort(hy) << 16) | __bfloat16_as_ushort(hx);
    lo = ((uint32_t)__bfloat16_as_ushort(ly) << 16) | __bfloat16_as_ushort(lx);
}

__device__ __forceinline__ void mma16(float* c, const uint32_t* a, const uint32_t* b) {
    asm volatile(
        "mma.sync.aligned.m16n8k16.row.col.f32.bf16.bf16.f32 "
        "{%0,%1,%2,%3},{%4,%5,%6,%7},{%8,%9},{%0,%1,%2,%3};"
        : "+f"(c[0]), "+f"(c[1]), "+f"(c[2]), "+f"(c[3])
        : "r"(a[0]), "r"(a[1]), "r"(a[2]), "r"(a[3]), "r"(b[0]), "r"(b[1]));
}

// BN_RELU: A element -> max(0, a*scale[k]+shift[k]) (fused bnfinal+BN+ReLU).
// HAS_EPI: C += bias[col], optional ReLU.
// COLSTATS: accumulate column sum/sumsq of C into g_stats.
template <bool BN_RELU, bool HAS_EPI, bool COLSTATS>
__global__ void __launch_bounds__(256, 2)
mma_gemm(const float* __restrict__ A, int lda,
         const float* __restrict__ B, int ldb,
         float* __restrict__ C, int ldc,
         int M, int K,
         const float* __restrict__ bias, int do_relu,
         const float* __restrict__ bng, const float* __restrict__ bnb) {
    // packed bf16x2 k-pairs: [row][kpair], 8 pairs used, pad to 9 for banks
    __shared__ uint32_t As_hi[128][9], As_lo[128][9];
    __shared__ uint32_t Bs_hi[128][9], Bs_lo[128][9];
    __shared__ float s_sc[H2];
    __shared__ float s_sh[H2];

    int tid = threadIdx.x;
    int wid = tid >> 5, lane = tid & 31;
    int qid = lane >> 2, rid = lane & 3;
    int warp_m = wid & 1, warp_n = wid >> 1;
    int m0 = blockIdx.x * 128, n0 = blockIdx.y * 128;

    if (BN_RELU) {
        float inv = 1.f / (float)M;
        float mu = g_stats[tid] * inv;
        float var = g_stats[H2 + tid] * inv - mu * mu;
        float rs = rsqrtf(var + 1e-5f);
        float sc = bng[tid] * rs;
        s_sc[tid] = sc;
        s_sh[tid] = bnb[tid] - mu * sc;
        __syncthreads();
    }

    float acc[4][4][4];
#pragma unroll
    for (int i = 0; i < 4; i++)
#pragma unroll
        for (int j = 0; j < 4; j++)
#pragma unroll
            for (int q = 0; q < 4; q++) acc[i][j][q] = 0.f;

    for (int k0 = 0; k0 < K; k0 += 16) {
        // ---- stage A tile: 128 rows x 16 k (512 float4 loads over 2 halves) ----
#pragma unroll
        for (int half = 0; half < 2; half++) {
            int idx = tid + half * 256;
            int row = idx >> 2;
            int cg = (idx & 3) << 2;     // k offset within step: 0,4,8,12
            int gm = m0 + row;
            float4 av = make_float4(0.f, 0.f, 0.f, 0.f);
            if (gm < M) av = *(const float4*)(A + (size_t)gm * lda + k0 + cg);
            if (BN_RELU) {
                int gk = k0 + cg;
                av.x = fmaxf(fmaf(av.x, s_sc[gk + 0], s_sh[gk + 0]), 0.f);
                av.y = fmaxf(fmaf(av.y, s_sc[gk + 1], s_sh[gk + 1]), 0.f);
                av.z = fmaxf(fmaf(av.z, s_sc[gk + 2], s_sh[gk + 2]), 0.f);
                av.w = fmaxf(fmaf(av.w, s_sc[gk + 3], s_sh[gk + 3]), 0.f);
                if (gm >= M) { av.x = av.y = av.z = av.w = 0.f; }
            }
            int kp = cg >> 1;  // k-pair index 0,2,4,6
            uint32_t h0, l0, h1, l1;
            splitpack(av.x, av.y, h0, l0);
            splitpack(av.z, av.w, h1, l1);
            As_hi[row][kp] = h0;     As_lo[row][kp] = l0;
            As_hi[row][kp + 1] = h1; As_lo[row][kp + 1] = l1;
        }
        // ---- stage B tile: 16 k x 128 n, packed along k into [n][kpair] ----
        {
            int kp = tid >> 5;           // 0..7 (one k-pair per warp)
            int nc = (lane) << 2;        // n offset 0..124
            const float* b0p = B + (size_t)(k0 + 2 * kp) * ldb + n0 + nc;
            const float* b1p = b0p + ldb;
            float4 r0 = *(const float4*)b0p;
            float4 r1 = *(const float4*)b1p;
            uint32_t h, l;
            splitpack(r0.x, r1.x, h, l); Bs_hi[nc + 0][kp] = h; Bs_lo[nc + 0][kp] = l;
            splitpack(r0.y, r1.y, h, l); Bs_hi[nc + 1][kp] = h; Bs_lo[nc + 1][kp] = l;
            splitpack(r0.z, r1.z, h, l); Bs_hi[nc + 2][kp] = h; Bs_lo[nc + 2][kp] = l;
            splitpack(r0.w, r1.w, h, l); Bs_hi[nc + 3][kp] = h; Bs_lo[nc + 3][kp] = l;
        }
        __syncthreads();

        // ---- compute: one k16 mma per (mt,nt) per pass, 3 passes ----
        uint32_t bh[4][2], bl[4][2];
#pragma unroll
        for (int nt = 0; nt < 4; nt++) {
            int nb = warp_n * 32 + nt * 8 + qid;
            bh[nt][0] = Bs_hi[nb][rid];     bh[nt][1] = Bs_hi[nb][rid + 4];
            bl[nt][0] = Bs_lo[nb][rid];     bl[nt][1] = Bs_lo[nb][rid + 4];
        }
#pragma unroll
        for (int mt = 0; mt < 4; mt++) {
            int rb = warp_m * 64 + mt * 16 + qid;
            uint32_t ah[4], al[4];
            ah[0] = As_hi[rb][rid];     ah[1] = As_hi[rb + 8][rid];
            ah[2] = As_hi[rb][rid + 4]; ah[3] = As_hi[rb + 8][rid + 4];
            al[0] = As_lo[rb][rid];     al[1] = As_lo[rb + 8][rid];
            al[2] = As_lo[rb][rid + 4]; al[3] = As_lo[rb + 8][rid + 4];
#pragma unroll
            for (int nt = 0; nt < 4; nt++) {
                mma16(acc[mt][nt], ah, bh[nt]);
                mma16(acc[mt][nt], ah, bl[nt]);
                mma16(acc[mt][nt], al, bh[nt]);
            }
        }
        __syncthreads();
    }

    int m_base = m0 + warp_m * 64;
    int n_base = n0 + warp_n * 32;

#pragma unroll
    for (int mt = 0; mt < 4; mt++) {
        int r0g = m_base + mt * 16 + qid;
        int r1g = r0g + 8;
#pragma unroll
        for (int nt = 0; nt < 4; nt++) {
            int cg = n_base + nt * 8 + rid * 2;
            float v0 = acc[mt][nt][0], v1 = acc[mt][nt][1];
            float v2 = acc[mt][nt][2], v3 = acc[mt][nt][3];
            if (HAS_EPI) {
                float b0v = bias[cg], b1v = bias[cg + 1];
                v0 += b0v; v1 += b1v; v2 += b0v; v3 += b1v;
                if (do_relu) {
                    v0 = fmaxf(v0, 0.f); v1 = fmaxf(v1, 0.f);
                    v2 = fmaxf(v2, 0.f); v3 = fmaxf(v3, 0.f);
                }
            }
            if (r0g < M) *(float2*)(C + (size_t)r0g * ldc + cg) = make_float2(v0, v1);
            if (r1g < M) *(float2*)(C + (size_t)r1g * ldc + cg) = make_float2(v2, v3);
        }
    }

    if (COLSTATS) {
#pragma unroll
        for (int nt = 0; nt < 4; nt++) {
            float s0 = 0.f, q0 = 0.f, s1 = 0.f, q1 = 0.f;
#pragma unroll
            for (int mt = 0; mt < 4; mt++) {
                int r0g = m_base + mt * 16 + qid;
                const float* c = acc[mt][nt];
                if (r0g < M)     { s0 += c[0]; q0 += c[0] * c[0]; s1 += c[1]; q1 += c[1] * c[1]; }
                if (r0g + 8 < M) { s0 += c[2]; q0 += c[2] * c[2]; s1 += c[3]; q1 += c[3] * c[3]; }
            }
#pragma unroll
            for (int o = 4; o < 32; o <<= 1) {
                s0 += __shfl_xor_sync(0xffffffff, s0, o);
                q0 += __shfl_xor_sync(0xffffffff, q0, o);
                s1 += __shfl_xor_sync(0xffffffff, s1, o);
                q1 += __shfl_xor_sync(0xffffffff, q1, o);
            }
            if (lane < 4) {
                int cg = n_base + nt * 8 + lane * 2;
                atomicAdd(&g_stats[cg], s0);
                atomicAdd(&g_stats[H2 + cg], q0);
                atomicAdd(&g_stats[cg + 1], s1);
                atomicAdd(&g_stats[H2 + cg + 1], q1);
            }
        }
    }
}

// ---------------- SpMM: Aext[:,0:128] = (A + I) @ h ----------------
__global__ void k_spmm(int n) {
    int wid = (blockIdx.x * blockDim.x + threadIdx.x) >> 5;
    int lane = threadIdx.x & 31;
    if (wid >= n) return;
    const float4* h4 = (const float4*)g_h;
    float4 acc = h4[(size_t)wid * 32 + lane];
    int e0 = g_rowptr[wid], e1 = g_rowptr[wid + 1];
    for (int e = e0; e < e1; e++) {
        int c = g_colidx[e];
        float4 hv = h4[(size_t)c * 32 + lane];
        acc.x += hv.x; acc.y += hv.y; acc.z += hv.z; acc.w += hv.w;
    }
    ((float4*)(g_Aext + (size_t)wid * KA))[lane] = acc;
}

// ---------------- fused head: per-graph mean pool + sigmoid + @disc_w ----------------
__global__ void k_head(const int* __restrict__ batch, const float* __restrict__ disc_w, int n) {
    __shared__ float srow[H];
    int g = blockIdx.x;
    int c = threadIdx.x;
    int lo = 0, hi = n;
    while (lo < hi) { int m = (lo + hi) >> 1; if (batch[m] < g) lo = m + 1; else hi = m; }
    int lo2 = lo, hi2 = n;
    while (lo2 < hi2) { int m = (lo2 + hi2) >> 1; if (batch[m] < g + 1) lo2 = m + 1; else hi2 = m; }
    float s = 0.f;
    for (int r = lo; r < lo2; r++) s += g_h[(size_t)r * H + c];
    float cnt = fmaxf((float)(lo2 - lo), 1.f);
    float sm = 1.f / (1.f + expf(-s / cnt));
    srow[c] = sm;
    __syncthreads();
    float acc = 0.f;
    for (int k = 0; k < H; k++) acc = fmaf(srow[k], disc_w[k * H + c], acc);
    g_s2[g * H + c] = acc;
}

__global__ void k_out(const int* __restrict__ batch, float* __restrict__ out, int n) {
    int wid = (blockIdx.x * blockDim.x + threadIdx.x) >> 5;
    int lane = threadIdx.x & 31;
    if (wid >= n) return;
    int g = batch[wid];
    int g2 = (g + 1) % GG;
    const float4* h4 = (const float4*)g_h;
    const float4* s4 = (const float4*)g_s2;
    float4 hv = h4[(size_t)wid * 32 + lane];
    float4 av = s4[(size_t)g * 32 + lane];
    float4 bv = s4[(size_t)g2 * 32 + lane];
    float p = hv.x * av.x + hv.y * av.y + hv.z * av.z + hv.w * av.w;
    float q = hv.x * bv.x + hv.y * bv.y + hv.z * bv.z + hv.w * bv.w;
#pragma unroll
    for (int off = 16; off > 0; off >>= 1) {
        p += __shfl_xor_sync(0xffffffff, p, off);
        q += __shfl_xor_sync(0xffffffff, q, off);
    }
    if (lane == 0) { out[wid] = p; out[n + wid] = q; }
}

// ---------------- host ----------------
extern "C" void kernel_launch(void* const* d_in, const int* in_sizes, int n_in,
                              void* d_out, int out_size) {
    const int*   x_ids     = (const int*)d_in[0];
    const int*   ei        = (const int*)d_in[1];
    const int*   batch     = (const int*)d_in[2];
    const float* edge_attr = (const float*)d_in[3];
    const float* node_emb  = (const float*)d_in[4];
    const float* enc_w     = (const float*)d_in[5];
    const float* enc_b     = (const float*)d_in[6];
    const float* w1        = (const float*)d_in[7];
    const float* b1        = (const float*)d_in[8];
    const float* bn_g      = (const float*)d_in[9];
    const float* bn_b      = (const float*)d_in[10];
    const float* w2        = (const float*)d_in[11];
    const float* b2        = (const float*)d_in[12];
    const float* disc_w    = (const float*)d_in[13];
    float* out = (float*)d_out;

    int n  = in_sizes[0];
    int ec = in_sizes[1] / 2;
    const int* src = ei;
    const int* dst = ei + ec;

    float *p_A0, *p_Aext, *p_z, *p_h, *p_W0p, *p_W1p;
    cudaGetSymbolAddress((void**)&p_A0,   g_A0);
    cudaGetSymbolAddress((void**)&p_Aext, g_Aext);
    cudaGetSymbolAddress((void**)&p_z,    g_z);
    cudaGetSymbolAddress((void**)&p_h,    g_h);
    cudaGetSymbolAddress((void**)&p_W0p,  g_W0p);
    cudaGetSymbolAddress((void**)&p_W1p,  g_W1p);

    int eb    = (ec + 255) / 256;
    int nb    = (n + 255) / 256;
    int nb512 = (n + 511) / 512;
    int mb    = (n + 127) / 128;
    int warpsB = (n * 32 + 255) / 256;

    // --- graph structure + layer-independent features ---
    k_zero_setup<<<(n * 16 + 255) / 256, 256>>>(n);
    k_edge_scatter<<<eb, 256>>>(src, dst, edge_attr, x_ids, ec);
    k_scan1<<<nb512, 512>>>(n);
    k_scan2<<<1, 128>>>(nb512, n);
    k_scan3<<<nb, 256>>>(n);
    k_fill<<<eb, 256>>>(src, dst, ec);
    k_finalize<<<nb, 256>>>(x_ids, n);

    // --- layer 0 ---
    k_w0prep<<<16, 256>>>(node_emb, enc_w, enc_b, w1, b1);
    mma_gemm<false, false, true><<<dim3(mb, 2), 256>>>(
        p_A0, K0W, p_W0p, H2, p_z, H2, n, K0W, nullptr, 0, nullptr, nullptr);
    mma_gemm<true, true, false><<<dim3(mb, 1), 256>>>(
        p_z, H2, w2, H, p_h, H, n, H2, b2, 1, bn_g, bn_b);

    // --- layer 1 ---
    k_w1prep<<<144, 256>>>(enc_w, enc_b, w1, b1);
    k_spmm<<<warpsB, 256>>>(n);
    mma_gemm<false, false, true><<<dim3(mb, 2), 256>>>(
        p_Aext, KA, p_W1p, H2, p_z, H2, n, KA, nullptr, 0, nullptr, nullptr);
    mma_gemm<true, true, false><<<dim3(mb, 1), 256>>>(
        p_z, H2, w2 + (size_t)H2 * H, H, p_h, H, n, H2, b2 + H, 0,
        bn_g + H2, bn_b + H2);

    // --- head ---
    k_head<<<GG, H>>>(batch, disc_w, n);
    k_out<<<warpsB, 256>>>(batch, out, n);
}

// round 4
// speedup vs baseline: 1.7766x; 1.1119x over previous
#include <cuda_runtime.h>
#include <cuda_bf16.h>
#include <math.h>
#include <stdint.h>

// Problem constants (fixed by the reference)
#define NV    50000
#define EE    800000
#define H     128
#define H2    256
#define GG    256
#define KA    144        // layer-1 A width (128 agg_h + 9 attr + deg+1 + 1 + 5 pad)
#define K0W   16         // layer-0 A width

// ---------------- scratch ----------------
__device__ int   g_deg[NV];
__device__ int   g_rowptr[NV + 1];
__device__ int   g_pos[NV];
__device__ int   g_colidx[EE];
__device__ int   g_eidx[EE];
__device__ int   g_tmpscan[NV];
__device__ int   g_blocksum[128];
__device__ int   g_blockoff[128];
__device__ float g_A0[(size_t)NV * K0W];
__device__ float g_Aext[(size_t)NV * KA];
__device__ float g_W0p[K0W * H2];
__device__ float g_W1p[KA * H2];
__device__ float g_z[(size_t)NV * H2];
__device__ float g_h[(size_t)NV * H];
__device__ float g_stats[2 * H2];
__device__ float g_s2[GG * H];

// ---------------- CSR build ----------------
__global__ void k_zero_deg(int n) {
    int i = blockIdx.x * blockDim.x + threadIdx.x;
    if (i < n) g_deg[i] = 0;
}

__global__ void k_count(const int* __restrict__ src, int ecount) {
    int e = blockIdx.x * blockDim.x + threadIdx.x;
    if (e < ecount) atomicAdd(&g_deg[src[e]], 1);
}

__global__ void k_scan1(int n) {
    __shared__ int s[512];
    int i = blockIdx.x * 512 + threadIdx.x;
    s[threadIdx.x] = (i < n) ? g_deg[i] : 0;
    __syncthreads();
#pragma unroll
    for (int off = 1; off < 512; off <<= 1) {
        int t = 0;
        if ((int)threadIdx.x >= off) t = s[threadIdx.x - off];
        __syncthreads();
        s[threadIdx.x] += t;
        __syncthreads();
    }
    if (i < n) g_tmpscan[i] = s[threadIdx.x];
    if (threadIdx.x == 511) g_blocksum[blockIdx.x] = s[511];
}

__global__ void k_scan2(int nb, int n) {
    __shared__ int sh[128];
    int t = threadIdx.x;
    int v = (t < nb) ? g_blocksum[t] : 0;
    sh[t] = v;
    __syncthreads();
#pragma unroll
    for (int off = 1; off < 128; off <<= 1) {
        int x = (t >= off) ? sh[t - off] : 0;
        __syncthreads();
        sh[t] += x;
        __syncthreads();
    }
    if (t < nb) g_blockoff[t] = sh[t] - v;
    if (t == 127) g_rowptr[n] = sh[127];
}

__global__ void k_scan3(int n) {
    int i = blockIdx.x * blockDim.x + threadIdx.x;
    if (i < n) {
        int r = g_tmpscan[i] - g_deg[i] + g_blockoff[i >> 9];
        g_rowptr[i] = r;
        g_pos[i] = r;
    }
}

__global__ void k_fill(const int* __restrict__ src, const int* __restrict__ dst, int ecount) {
    int e = blockIdx.x * blockDim.x + threadIdx.x;
    if (e >= ecount) return;
    int idx = atomicAdd(&g_pos[src[e]], 1);
    g_colidx[idx] = dst[e];
    g_eidx[idx] = e;
}

// Per-node gather: attr sums, x_id counts, build Aext tail + A0 row. No atomics.
__global__ void k_node(const int* __restrict__ x_ids, const float* __restrict__ attr, int n) {
    int wid = (blockIdx.x * blockDim.x + threadIdx.x) >> 5;
    int lane = threadIdx.x & 31;
    if (wid >= n) return;
    int e0 = g_rowptr[wid], e1 = g_rowptr[wid + 1];
    float a[9];
#pragma unroll
    for (int j = 0; j < 9; j++) a[j] = 0.f;
    int bc = 0;
    for (int e = e0 + lane; e < e1; e += 32) {
        int c = g_colidx[e];
        int eid = g_eidx[e];
        bc += x_ids[c];
        const float* ap = attr + (size_t)eid * 9;
#pragma unroll
        for (int j = 0; j < 9; j++) a[j] += ap[j];
    }
#pragma unroll
    for (int o = 16; o > 0; o >>= 1) {
#pragma unroll
        for (int j = 0; j < 9; j++) a[j] += __shfl_xor_sync(0xffffffff, a[j], o);
        bc += __shfl_xor_sync(0xffffffff, bc, o);
    }
    if (lane == 0) {
        a[7] += 1.0f;                                   // self-loop one-hot
        float dp1 = (float)(e1 - e0 + 1);
        float bfull = (float)(bc + x_ids[wid]);
        float* tail = &g_Aext[(size_t)wid * KA + 128];
#pragma unroll
        for (int j = 0; j < 9; j++) tail[j] = a[j];
        tail[9]  = dp1;
        tail[10] = 1.0f;
        tail[11] = 0.f; tail[12] = 0.f; tail[13] = 0.f; tail[14] = 0.f; tail[15] = 0.f;
        float* a0 = &g_A0[(size_t)wid * K0W];
        a0[0] = dp1 - bfull;
        a0[1] = bfull;
#pragma unroll
        for (int j = 0; j < 9; j++) a0[2 + j] = a[j];
        a0[11] = dp1;
        a0[12] = 1.f;
        a0[13] = 0.f; a0[14] = 0.f; a0[15] = 0.f;
    }
}

// ---------------- folded weight prep (also zeroes g_stats) ----------------
__global__ void k_w0prep(const float* __restrict__ node_emb, const float* __restrict__ enc_w,
                         const float* __restrict__ enc_b, const float* __restrict__ w1,
                         const float* __restrict__ b1) {
    int tid = blockIdx.x * blockDim.x + threadIdx.x;
    if (tid < 2 * H2) g_stats[tid] = 0.f;
    if (tid >= K0W * H2) return;
    int row = tid >> 8, col = tid & 255;
    float val = 0.f;
    if (row < 2) {
        for (int k = 0; k < H; k++) val += node_emb[row * H + k] * w1[k * H2 + col];
    } else if (row < 11) {
        int j = row - 2;
        for (int k = 0; k < H; k++) val += enc_w[j * H + k] * w1[(H + k) * H2 + col];
    } else if (row == 11) {
        for (int k = 0; k < H; k++) val += enc_b[k] * w1[(H + k) * H2 + col];
    } else if (row == 12) {
        val = b1[col];
    }
    g_W0p[tid] = val;
}

__global__ void k_w1prep(const float* __restrict__ enc_w, const float* __restrict__ enc_b,
                         const float* __restrict__ w1, const float* __restrict__ b1) {
    int tid = blockIdx.x * blockDim.x + threadIdx.x;
    if (tid < 2 * H2) g_stats[tid] = 0.f;
    if (tid >= KA * H2) return;
    int row = tid >> 8, col = tid & 255;
    const float* w1L = w1 + H2 * H2;
    float val = 0.f;
    if (row < 128) {
        val = w1L[row * H2 + col];
    } else if (row < 137) {
        int j = row - 128;
        for (int k = 0; k < H; k++) val += enc_w[9 * H + j * H + k] * w1L[(H + k) * H2 + col];
    } else if (row == 137) {
        for (int k = 0; k < H; k++) val += enc_b[H + k] * w1L[(H + k) * H2 + col];
    } else if (row == 138) {
        val = b1[H2 + col];
    }
    g_W1p[tid] = val;
}

// ---------------- precision-compensated bf16 GEMM, double-buffered ----------------
__device__ __forceinline__ void splitpack(float x, float y, uint32_t& hi, uint32_t& lo) {
    __nv_bfloat16 hx = __float2bfloat16_rn(x);
    __nv_bfloat16 hy = __float2bfloat16_rn(y);
    __nv_bfloat16 lx = __float2bfloat16_rn(x - __bfloat162float(hx));
    __nv_bfloat16 ly = __float2bfloat16_rn(y - __bfloat162float(hy));
    hi = ((uint32_t)__bfloat16_as_ushort(hy) << 16) | __bfloat16_as_ushort(hx);
    lo = ((uint32_t)__bfloat16_as_ushort(ly) << 16) | __bfloat16_as_ushort(lx);
}

__device__ __forceinline__ void mma16(float* c, const uint32_t* a, const uint32_t* b) {
    asm volatile(
        "mma.sync.aligned.m16n8k16.row.col.f32.bf16.bf16.f32 "
        "{%0,%1,%2,%3},{%4,%5,%6,%7},{%8,%9},{%0,%1,%2,%3};"
        : "+f"(c[0]), "+f"(c[1]), "+f"(c[2]), "+f"(c[3])
        : "r"(a[0]), "r"(a[1]), "r"(a[2]), "r"(a[3]), "r"(b[0]), "r"(b[1]));
}

template <bool BN_RELU, bool HAS_EPI, bool COLSTATS>
__global__ void __launch_bounds__(256, 2)
mma_gemm(const float* __restrict__ A, int lda,
         const float* __restrict__ B, int ldb,
         float* __restrict__ C, int ldc,
         int M, int K,
         const float* __restrict__ bias, int do_relu,
         const float* __restrict__ bng, const float* __restrict__ bnb) {
    __shared__ uint32_t As_hi[2][128][9], As_lo[2][128][9];
    __shared__ uint32_t Bs_hi[2][128][9], Bs_lo[2][128][9];
    __shared__ float s_sc[H2];
    __shared__ float s_sh[H2];

    int tid = threadIdx.x;
    int wid = tid >> 5, lane = tid & 31;
    int qid = lane >> 2, rid = lane & 3;
    int warp_m = wid & 1, warp_n = wid >> 1;
    int m0 = blockIdx.x * 128, n0 = blockIdx.y * 128;

    if (BN_RELU) {
        float inv = 1.f / (float)M;
        float mu = g_stats[tid] * inv;
        float var = g_stats[H2 + tid] * inv - mu * mu;
        float rs = rsqrtf(var + 1e-5f);
        float sc = bng[tid] * rs;
        s_sc[tid] = sc;
        s_sh[tid] = bnb[tid] - mu * sc;
        __syncthreads();
    }

    float acc[4][4][4];
#pragma unroll
    for (int i = 0; i < 4; i++)
#pragma unroll
        for (int j = 0; j < 4; j++)
#pragma unroll
            for (int q = 0; q < 4; q++) acc[i][j][q] = 0.f;

    // ---- load assignments ----
    int arow0 = tid >> 2;              // 0..63
    int arow1 = arow0 + 64;            // 64..127
    int acg   = (tid & 3) << 2;        // k offset 0,4,8,12
    bool am0 = (m0 + arow0) < M;
    bool am1 = (m0 + arow1) < M;
    const float* Ap0 = A + (size_t)(m0 + arow0) * lda + acg;
    const float* Ap1 = A + (size_t)(m0 + arow1) * lda + acg;
    int kp = tid >> 5;                 // 0..7 (k-pair per warp)
    int nc = lane << 2;                // n offset 0..124
    const float* Bp = B + (size_t)(2 * kp) * ldb + n0 + nc;

    const float4 z4 = make_float4(0.f, 0.f, 0.f, 0.f);
    float4 ra0 = am0 ? *(const float4*)Ap0 : z4;
    float4 ra1 = am1 ? *(const float4*)Ap1 : z4;
    float4 rb0 = *(const float4*)Bp;
    float4 rb1 = *(const float4*)(Bp + ldb);

    int buf = 0;
    for (int k0 = 0; k0 < K; k0 += 16) {
        // ---- split + store current tile ----
        {
            float4 av = ra0;
            if (BN_RELU) {
                int gk = k0 + acg;
                av.x = fmaxf(fmaf(av.x, s_sc[gk + 0], s_sh[gk + 0]), 0.f);
                av.y = fmaxf(fmaf(av.y, s_sc[gk + 1], s_sh[gk + 1]), 0.f);
                av.z = fmaxf(fmaf(av.z, s_sc[gk + 2], s_sh[gk + 2]), 0.f);
                av.w = fmaxf(fmaf(av.w, s_sc[gk + 3], s_sh[gk + 3]), 0.f);
                if (!am0) { av.x = av.y = av.z = av.w = 0.f; }
            }
            int kpa = acg >> 1;
            uint32_t h0, l0, h1, l1;
            splitpack(av.x, av.y, h0, l0);
            splitpack(av.z, av.w, h1, l1);
            As_hi[buf][arow0][kpa] = h0;     As_lo[buf][arow0][kpa] = l0;
            As_hi[buf][arow0][kpa + 1] = h1; As_lo[buf][arow0][kpa + 1] = l1;

            av = ra1;
            if (BN_RELU) {
                int gk = k0 + acg;
                av.x = fmaxf(fmaf(av.x, s_sc[gk + 0], s_sh[gk + 0]), 0.f);
                av.y = fmaxf(fmaf(av.y, s_sc[gk + 1], s_sh[gk + 1]), 0.f);
                av.z = fmaxf(fmaf(av.z, s_sc[gk + 2], s_sh[gk + 2]), 0.f);
                av.w = fmaxf(fmaf(av.w, s_sc[gk + 3], s_sh[gk + 3]), 0.f);
                if (!am1) { av.x = av.y = av.z = av.w = 0.f; }
            }
            splitpack(av.x, av.y, h0, l0);
            splitpack(av.z, av.w, h1, l1);
            As_hi[buf][arow1][kpa] = h0;     As_lo[buf][arow1][kpa] = l0;
            As_hi[buf][arow1][kpa + 1] = h1; As_lo[buf][arow1][kpa + 1] = l1;

            uint32_t h, l;
            splitpack(rb0.x, rb1.x, h, l); Bs_hi[buf][nc + 0][kp] = h; Bs_lo[buf][nc + 0][kp] = l;
            splitpack(rb0.y, rb1.y, h, l); Bs_hi[buf][nc + 1][kp] = h; Bs_lo[buf][nc + 1][kp] = l;
            splitpack(rb0.z, rb1.z, h, l); Bs_hi[buf][nc + 2][kp] = h; Bs_lo[buf][nc + 2][kp] = l;
            splitpack(rb0.w, rb1.w, h, l); Bs_hi[buf][nc + 3][kp] = h; Bs_lo[buf][nc + 3][kp] = l;
        }
        __syncthreads();

        // ---- prefetch next tile into registers ----
        if (k0 + 16 < K) {
            int kn = k0 + 16;
            ra0 = am0 ? *(const float4*)(Ap0 + kn) : z4;
            ra1 = am1 ? *(const float4*)(Ap1 + kn) : z4;
            const float* bp = Bp + (size_t)kn * ldb;
            rb0 = *(const float4*)bp;
            rb1 = *(const float4*)(bp + ldb);
        }

        // ---- compute from smem[buf]: 3-pass compensated bf16 ----
        uint32_t bh[4][2], bl[4][2];
#pragma unroll
        for (int nt = 0; nt < 4; nt++) {
            int nb = warp_n * 32 + nt * 8 + qid;
            bh[nt][0] = Bs_hi[buf][nb][rid];     bh[nt][1] = Bs_hi[buf][nb][rid + 4];
            bl[nt][0] = Bs_lo[buf][nb][rid];     bl[nt][1] = Bs_lo[buf][nb][rid + 4];
        }
#pragma unroll
        for (int mt = 0; mt < 4; mt++) {
            int rb = warp_m * 64 + mt * 16 + qid;
            uint32_t ah[4], al[4];
            ah[0] = As_hi[buf][rb][rid];     ah[1] = As_hi[buf][rb + 8][rid];
            ah[2] = As_hi[buf][rb][rid + 4]; ah[3] = As_hi[buf][rb + 8][rid + 4];
            al[0] = As_lo[buf][rb][rid];     al[1] = As_lo[buf][rb + 8][rid];
            al[2] = As_lo[buf][rb][rid + 4]; al[3] = As_lo[buf][rb + 8][rid + 4];
#pragma unroll
            for (int nt = 0; nt < 4; nt++) {
                mma16(acc[mt][nt], ah, bh[nt]);
                mma16(acc[mt][nt], ah, bl[nt]);
                mma16(acc[mt][nt], al, bh[nt]);
            }
        }
        buf ^= 1;
    }

    int m_base = m0 + warp_m * 64;
    int n_base = n0 + warp_n * 32;

#pragma unroll
    for (int mt = 0; mt < 4; mt++) {
        int r0g = m_base + mt * 16 + qid;
        int r1g = r0g + 8;
#pragma unroll
        for (int nt = 0; nt < 4; nt++) {
            int cg = n_base + nt * 8 + rid * 2;
            float v0 = acc[mt][nt][0], v1 = acc[mt][nt][1];
            float v2 = acc[mt][nt][2], v3 = acc[mt][nt][3];
            if (HAS_EPI) {
                float b0v = bias[cg], b1v = bias[cg + 1];
                v0 += b0v; v1 += b1v; v2 += b0v; v3 += b1v;
                if (do_relu) {
                    v0 = fmaxf(v0, 0.f); v1 = fmaxf(v1, 0.f);
                    v2 = fmaxf(v2, 0.f); v3 = fmaxf(v3, 0.f);
                }
            }
            if (r0g < M) *(float2*)(C + (size_t)r0g * ldc + cg) = make_float2(v0, v1);
            if (r1g < M) *(float2*)(C + (size_t)r1g * ldc + cg) = make_float2(v2, v3);
        }
    }

    if (COLSTATS) {
#pragma unroll
        for (int nt = 0; nt < 4; nt++) {
            float s0 = 0.f, q0 = 0.f, s1 = 0.f, q1 = 0.f;
#pragma unroll
            for (int mt = 0; mt < 4; mt++) {
                int r0g = m_base + mt * 16 + qid;
                const float* c = acc[mt][nt];
                if (r0g < M)     { s0 += c[0]; q0 += c[0] * c[0]; s1 += c[1]; q1 += c[1] * c[1]; }
                if (r0g + 8 < M) { s0 += c[2]; q0 += c[2] * c[2]; s1 += c[3]; q1 += c[3] * c[3]; }
            }
#pragma unroll
            for (int o = 4; o < 32; o <<= 1) {
                s0 += __shfl_xor_sync(0xffffffff, s0, o);
                q0 += __shfl_xor_sync(0xffffffff, q0, o);
                s1 += __shfl_xor_sync(0xffffffff, s1, o);
                q1 += __shfl_xor_sync(0xffffffff, q1, o);
            }
            if (lane < 4) {
                int cg = n_base + nt * 8 + lane * 2;
                atomicAdd(&g_stats[cg], s0);
                atomicAdd(&g_stats[H2 + cg], q0);
                atomicAdd(&g_stats[cg + 1], s1);
                atomicAdd(&g_stats[H2 + cg + 1], q1);
            }
        }
    }
}

// ---------------- SpMM: Aext[:,0:128] = (A + I) @ h ----------------
__global__ void k_spmm(int n) {
    int wid = (blockIdx.x * blockDim.x + threadIdx.x) >> 5;
    int lane = threadIdx.x & 31;
    if (wid >= n) return;
    const float4* h4 = (const float4*)g_h;
    float4 acc = h4[(size_t)wid * 32 + lane];
    int e0 = g_rowptr[wid], e1 = g_rowptr[wid + 1];
    for (int e = e0; e < e1; e++) {
        int c = g_colidx[e];
        float4 hv = h4[(size_t)c * 32 + lane];
        acc.x += hv.x; acc.y += hv.y; acc.z += hv.z; acc.w += hv.w;
    }
    ((float4*)(g_Aext + (size_t)wid * KA))[lane] = acc;
}

// ---------------- fused head ----------------
__global__ void k_head(const int* __restrict__ batch, const float* __restrict__ disc_w, int n) {
    __shared__ float srow[H];
    int g = blockIdx.x;
    int c = threadIdx.x;
    int lo = 0, hi = n;
    while (lo < hi) { int m = (lo + hi) >> 1; if (batch[m] < g) lo = m + 1; else hi = m; }
    int lo2 = lo, hi2 = n;
    while (lo2 < hi2) { int m = (lo2 + hi2) >> 1; if (batch[m] < g + 1) lo2 = m + 1; else hi2 = m; }
    float s = 0.f;
    for (int r = lo; r < lo2; r++) s += g_h[(size_t)r * H + c];
    float cnt = fmaxf((float)(lo2 - lo), 1.f);
    float sm = 1.f / (1.f + expf(-s / cnt));
    srow[c] = sm;
    __syncthreads();
    float acc = 0.f;
    for (int k = 0; k < H; k++) acc = fmaf(srow[k], disc_w[k * H + c], acc);
    g_s2[g * H + c] = acc;
}

__global__ void k_out(const int* __restrict__ batch, float* __restrict__ out, int n) {
    int wid = (blockIdx.x * blockDim.x + threadIdx.x) >> 5;
    int lane = threadIdx.x & 31;
    if (wid >= n) return;
    int g = batch[wid];
    int g2 = (g + 1) % GG;
    const float4* h4 = (const float4*)g_h;
    const float4* s4 = (const float4*)g_s2;
    float4 hv = h4[(size_t)wid * 32 + lane];
    float4 av = s4[(size_t)g * 32 + lane];
    float4 bv = s4[(size_t)g2 * 32 + lane];
    float p = hv.x * av.x + hv.y * av.y + hv.z * av.z + hv.w * av.w;
    float q = hv.x * bv.x + hv.y * bv.y + hv.z * bv.z + hv.w * bv.w;
#pragma unroll
    for (int off = 16; off > 0; off >>= 1) {
        p += __shfl_xor_sync(0xffffffff, p, off);
        q += __shfl_xor_sync(0xffffffff, q, off);
    }
    if (lane == 0) { out[wid] = p; out[n + wid] = q; }
}

// ---------------- host ----------------
extern "C" void kernel_launch(void* const* d_in, const int* in_sizes, int n_in,
                              void* d_out, int out_size) {
    const int*   x_ids     = (const int*)d_in[0];
    const int*   ei        = (const int*)d_in[1];
    const int*   batch     = (const int*)d_in[2];
    const float* edge_attr = (const float*)d_in[3];
    const float* node_emb  = (const float*)d_in[4];
    const float* enc_w     = (const float*)d_in[5];
    const float* enc_b     = (const float*)d_in[6];
    const float* w1        = (const float*)d_in[7];
    const float* b1        = (const float*)d_in[8];
    const float* bn_g      = (const float*)d_in[9];
    const float* bn_b      = (const float*)d_in[10];
    const float* w2        = (const float*)d_in[11];
    const float* b2        = (const float*)d_in[12];
    const float* disc_w    = (const float*)d_in[13];
    float* out = (float*)d_out;

    int n  = in_sizes[0];
    int ec = in_sizes[1] / 2;
    const int* src = ei;
    const int* dst = ei + ec;

    float *p_A0, *p_Aext, *p_z, *p_h, *p_W0p, *p_W1p;
    cudaGetSymbolAddress((void**)&p_A0,   g_A0);
    cudaGetSymbolAddress((void**)&p_Aext, g_Aext);
    cudaGetSymbolAddress((void**)&p_z,    g_z);
    cudaGetSymbolAddress((void**)&p_h,    g_h);
    cudaGetSymbolAddress((void**)&p_W0p,  g_W0p);
    cudaGetSymbolAddress((void**)&p_W1p,  g_W1p);

    int eb    = (ec + 255) / 256;
    int nb    = (n + 255) / 256;
    int nb512 = (n + 511) / 512;
    int mb    = (n + 127) / 128;
    int warpsB = (n * 32 + 255) / 256;

    // --- graph structure + per-node features (atomic-free aggregation) ---
    k_zero_deg<<<nb, 256>>>(n);
    k_count<<<eb, 256>>>(src, ec);
    k_scan1<<<nb512, 512>>>(n);
    k_scan2<<<1, 128>>>(nb512, n);
    k_scan3<<<nb, 256>>>(n);
    k_fill<<<eb, 256>>>(src, dst, ec);
    k_node<<<warpsB, 256>>>(x_ids, edge_attr, n);

    // --- layer 0 ---
    k_w0prep<<<16, 256>>>(node_emb, enc_w, enc_b, w1, b1);
    mma_gemm<false, false, true><<<dim3(mb, 2), 256>>>(
        p_A0, K0W, p_W0p, H2, p_z, H2, n, K0W, nullptr, 0, nullptr, nullptr);
    mma_gemm<true, true, false><<<dim3(mb, 1), 256>>>(
        p_z, H2, w2, H, p_h, H, n, H2, b2, 1, bn_g, bn_b);

    // --- layer 1 ---
    k_w1prep<<<144, 256>>>(enc_w, enc_b, w1, b1);
    k_spmm<<<warpsB, 256>>>(n);
    mma_gemm<false, false, true><<<dim3(mb, 2), 256>>>(
        p_Aext, KA, p_W1p, H2, p_z, H2, n, KA, nullptr, 0, nullptr, nullptr);
    mma_gemm<true, true, false><<<dim3(mb, 1), 256>>>(
        p_z, H2, w2 + (size_t)H2 * H, H, p_h, H, n, H2, b2 + H, 0,
        bn_g + H2, bn_b + H2);

    // --- head ---
    k_head<<<GG, H>>>(batch, disc_w, n);
    k_out<<<warpsB, 256>>>(batch, out, n);
}

// round 5
// speedup vs baseline: 1.8065x; 1.0168x over previous
#include <cuda_runtime.h>
#include <cuda_bf16.h>
#include <math.h>
#include <stdint.h>

// Problem constants (fixed by the reference)
#define NV    50000
#define EE    800000
#define H     128
#define H2    256
#define GG    256
#define KA    144        // layer-1 A width in k (128 agg_h + 9 attr + deg+1 + 1 + 5 pad)
#define KAP   72         // KA/2 kpairs
#define K0W   16         // layer-0 A width
#define K0P   8

// ---------------- scratch ----------------
__device__ int   g_deg[NV];
__device__ int   g_rowptr[NV + 1];
__device__ int   g_pos[NV];
__device__ int   g_colidx[EE];
__device__ int   g_eidx[EE];
__device__ int   g_tmpscan[NV];
__device__ int   g_blocksum[128];
__device__ int   g_blockoff[128];
__device__ __align__(16) uint32_t g_A0h[(size_t)NV * K0P];
__device__ __align__(16) uint32_t g_A0l[(size_t)NV * K0P];
__device__ __align__(16) uint32_t g_Aexth[(size_t)NV * KAP];
__device__ __align__(16) uint32_t g_Aextl[(size_t)NV * KAP];
__device__ __align__(16) uint32_t g_W0ph[K0P * H2];
__device__ __align__(16) uint32_t g_W0pl[K0P * H2];
__device__ __align__(16) uint32_t g_W1ph[KAP * H2];
__device__ __align__(16) uint32_t g_W1pl[KAP * H2];
__device__ __align__(16) uint32_t g_W2h[2 * 128 * H];
__device__ __align__(16) uint32_t g_W2l[2 * 128 * H];
__device__ float g_z[(size_t)NV * H2];
__device__ float g_h[(size_t)NV * H];
__device__ float g_stats[2 * H2];
__device__ float g_s2[GG * H];

// ---------------- helpers ----------------
__device__ __forceinline__ void splitpack(float x, float y, uint32_t& hi, uint32_t& lo) {
    __nv_bfloat16 hx = __float2bfloat16_rn(x);
    __nv_bfloat16 hy = __float2bfloat16_rn(y);
    __nv_bfloat16 lx = __float2bfloat16_rn(x - __bfloat162float(hx));
    __nv_bfloat16 ly = __float2bfloat16_rn(y - __bfloat162float(hy));
    hi = ((uint32_t)__bfloat16_as_ushort(hy) << 16) | __bfloat16_as_ushort(hx);
    lo = ((uint32_t)__bfloat16_as_ushort(ly) << 16) | __bfloat16_as_ushort(lx);
}

__device__ __forceinline__ void mma16(float* c, const uint32_t* a, const uint32_t* b) {
    asm volatile(
        "mma.sync.aligned.m16n8k16.row.col.f32.bf16.bf16.f32 "
        "{%0,%1,%2,%3},{%4,%5,%6,%7},{%8,%9},{%0,%1,%2,%3};"
        : "+f"(c[0]), "+f"(c[1]), "+f"(c[2]), "+f"(c[3])
        : "r"(a[0]), "r"(a[1]), "r"(a[2]), "r"(a[3]), "r"(b[0]), "r"(b[1]));
}

__device__ __forceinline__ void ldsm4(uint32_t& r0, uint32_t& r1, uint32_t& r2, uint32_t& r3,
                                      uint32_t addr) {
    asm volatile("ldmatrix.sync.aligned.m8n8.x4.shared.b16 {%0,%1,%2,%3}, [%4];"
                 : "=r"(r0), "=r"(r1), "=r"(r2), "=r"(r3) : "r"(addr));
}

// ---------------- CSR build ----------------
__global__ void k_zero_deg(int n) {
    int i = blockIdx.x * blockDim.x + threadIdx.x;
    if (i < n) g_deg[i] = 0;
}

__global__ void k_count(const int* __restrict__ src, int ecount) {
    int e = blockIdx.x * blockDim.x + threadIdx.x;
    if (e < ecount) atomicAdd(&g_deg[src[e]], 1);
}

__global__ void k_scan1(int n) {
    __shared__ int s[512];
    int i = blockIdx.x * 512 + threadIdx.x;
    s[threadIdx.x] = (i < n) ? g_deg[i] : 0;
    __syncthreads();
#pragma unroll
    for (int off = 1; off < 512; off <<= 1) {
        int t = 0;
        if ((int)threadIdx.x >= off) t = s[threadIdx.x - off];
        __syncthreads();
        s[threadIdx.x] += t;
        __syncthreads();
    }
    if (i < n) g_tmpscan[i] = s[threadIdx.x];
    if (threadIdx.x == 511) g_blocksum[blockIdx.x] = s[511];
}

__global__ void k_scan2(int nb, int n) {
    __shared__ int sh[128];
    int t = threadIdx.x;
    int v = (t < nb) ? g_blocksum[t] : 0;
    sh[t] = v;
    __syncthreads();
#pragma unroll
    for (int off = 1; off < 128; off <<= 1) {
        int x = (t >= off) ? sh[t - off] : 0;
        __syncthreads();
        sh[t] += x;
        __syncthreads();
    }
    if (t < nb) g_blockoff[t] = sh[t] - v;
    if (t == 127) g_rowptr[n] = sh[127];
}

__global__ void k_scan3(int n) {
    int i = blockIdx.x * blockDim.x + threadIdx.x;
    if (i < n) {
        int r = g_tmpscan[i] - g_deg[i] + g_blockoff[i >> 9];
        g_rowptr[i] = r;
        g_pos[i] = r;
    }
}

__global__ void k_fill(const int* __restrict__ src, const int* __restrict__ dst, int ecount) {
    int e = blockIdx.x * blockDim.x + threadIdx.x;
    if (e >= ecount) return;
    int idx = atomicAdd(&g_pos[src[e]], 1);
    g_colidx[idx] = dst[e];
    g_eidx[idx] = e;
}

// Per-node gather: attr sums, x_id counts; write PRE-SPLIT A0 row + Aext tail kpairs.
__global__ void k_node(const int* __restrict__ x_ids, const float* __restrict__ attr, int n) {
    int wid = (blockIdx.x * blockDim.x + threadIdx.x) >> 5;
    int lane = threadIdx.x & 31;
    if (wid >= n) return;
    int e0 = g_rowptr[wid], e1 = g_rowptr[wid + 1];
    float a[9];
#pragma unroll
    for (int j = 0; j < 9; j++) a[j] = 0.f;
    int bc = 0;
    for (int e = e0 + lane; e < e1; e += 32) {
        int c = g_colidx[e];
        int eid = g_eidx[e];
        bc += x_ids[c];
        const float* ap = attr + (size_t)eid * 9;
#pragma unroll
        for (int j = 0; j < 9; j++) a[j] += ap[j];
    }
#pragma unroll
    for (int o = 16; o > 0; o >>= 1) {
#pragma unroll
        for (int j = 0; j < 9; j++) a[j] += __shfl_xor_sync(0xffffffff, a[j], o);
        bc += __shfl_xor_sync(0xffffffff, bc, o);
    }
    if (lane == 0) {
        a[7] += 1.0f;                                   // self-loop one-hot
        float dp1 = (float)(e1 - e0 + 1);
        float bfull = (float)(bc + x_ids[wid]);
        float t[16];
#pragma unroll
        for (int j = 0; j < 9; j++) t[j] = a[j];
        t[9] = dp1; t[10] = 1.f;
        t[11] = 0.f; t[12] = 0.f; t[13] = 0.f; t[14] = 0.f; t[15] = 0.f;
        uint32_t h, l;
#pragma unroll
        for (int p = 0; p < 8; p++) {
            splitpack(t[2 * p], t[2 * p + 1], h, l);
            g_Aexth[(size_t)wid * KAP + 64 + p] = h;
            g_Aextl[(size_t)wid * KAP + 64 + p] = l;
        }
        float a0v[16];
        a0v[0] = dp1 - bfull;
        a0v[1] = bfull;
#pragma unroll
        for (int j = 0; j < 9; j++) a0v[2 + j] = a[j];
        a0v[11] = dp1; a0v[12] = 1.f;
        a0v[13] = 0.f; a0v[14] = 0.f; a0v[15] = 0.f;
#pragma unroll
        for (int p = 0; p < 8; p++) {
            splitpack(a0v[2 * p], a0v[2 * p + 1], h, l);
            g_A0h[(size_t)wid * K0P + p] = h;
            g_A0l[(size_t)wid * K0P + p] = l;
        }
    }
}

// ---------------- folded + split weight prep ----------------
__device__ __forceinline__ float w0row(int row, int col,
                                       const float* node_emb, const float* enc_w,
                                       const float* enc_b, const float* w1,
                                       const float* b1) {
    float val = 0.f;
    if (row < 2) {
        for (int k = 0; k < H; k++) val += node_emb[row * H + k] * w1[k * H2 + col];
    } else if (row < 11) {
        int j = row - 2;
        for (int k = 0; k < H; k++) val += enc_w[j * H + k] * w1[(H + k) * H2 + col];
    } else if (row == 11) {
        for (int k = 0; k < H; k++) val += enc_b[k] * w1[(H + k) * H2 + col];
    } else if (row == 12) {
        val = b1[col];
    }
    return val;
}

__global__ void k_w0prep(const float* __restrict__ node_emb, const float* __restrict__ enc_w,
                         const float* __restrict__ enc_b, const float* __restrict__ w1,
                         const float* __restrict__ b1) {
    int tid = blockIdx.x * blockDim.x + threadIdx.x;  // 8*256
    if (tid < 2 * H2) g_stats[tid] = 0.f;
    if (tid >= K0P * H2) return;
    int kp = tid >> 8, col = tid & 255;
    float v0 = w0row(2 * kp, col, node_emb, enc_w, enc_b, w1, b1);
    float v1 = w0row(2 * kp + 1, col, node_emb, enc_w, enc_b, w1, b1);
    uint32_t h, l;
    splitpack(v0, v1, h, l);
    g_W0ph[kp * H2 + col] = h;
    g_W0pl[kp * H2 + col] = l;
}

__device__ __forceinline__ float w1row(int row, int col,
                                       const float* enc_w, const float* enc_b,
                                       const float* w1, const float* b1) {
    const float* w1L = w1 + H2 * H2;
    float val = 0.f;
    if (row < 128) {
        val = w1L[row * H2 + col];
    } else if (row < 137) {
        int j = row - 128;
        for (int k = 0; k < H; k++) val += enc_w[9 * H + j * H + k] * w1L[(H + k) * H2 + col];
    } else if (row == 137) {
        for (int k = 0; k < H; k++) val += enc_b[H + k] * w1L[(H + k) * H2 + col];
    } else if (row == 138) {
        val = b1[H2 + col];
    }
    return val;
}

__global__ void k_w1prep(const float* __restrict__ enc_w, const float* __restrict__ enc_b,
                         const float* __restrict__ w1, const float* __restrict__ b1) {
    int tid = blockIdx.x * blockDim.x + threadIdx.x;  // 72*256
    if (tid < 2 * H2) g_stats[tid] = 0.f;
    if (tid >= KAP * H2) return;
    int kp = tid >> 8, col = tid & 255;
    float v0 = w1row(2 * kp, col, enc_w, enc_b, w1, b1);
    float v1 = w1row(2 * kp + 1, col, enc_w, enc_b, w1, b1);
    uint32_t h, l;
    splitpack(v0, v1, h, l);
    g_W1ph[kp * H2 + col] = h;
    g_W1pl[kp * H2 + col] = l;
}

__global__ void k_w2prep(const float* __restrict__ w2) {
    int tid = blockIdx.x * blockDim.x + threadIdx.x;  // 2*128*128
    if (tid >= 2 * 128 * H) return;
    int layer = tid / (128 * H);
    int r = tid - layer * 128 * H;
    int kp = r / H, col = r - kp * H;
    const float* w = w2 + (size_t)layer * H2 * H;
    float v0 = w[(2 * kp) * H + col];
    float v1 = w[(2 * kp + 1) * H + col];
    uint32_t h, l;
    splitpack(v0, v1, h, l);
    g_W2h[tid] = h;
    g_W2l[tid] = l;
}

// ---------------- compensated bf16 GEMM, ldmatrix A-frags, double-buffered ----------------
// PRESPLIT: A given as packed bf16 hi/lo kpair arrays (Ah/Al, lda in kpairs).
//           else A is fp32 (Af, lda in floats) with fused BN(+ReLU) from g_stats.
// B always pre-split kpair-major [kp][ldbu].
#define ABUF (128 * 12 * 4)

template <bool PRESPLIT, bool HAS_EPI, bool COLSTATS>
__global__ void __launch_bounds__(256, 2)
mma_gemm(const uint32_t* __restrict__ Ah, const uint32_t* __restrict__ Al,
         const float* __restrict__ Af, int lda,
         const uint32_t* __restrict__ Bh, const uint32_t* __restrict__ Bl, int ldbu,
         float* __restrict__ C, int ldc, int M, int K,
         const float* __restrict__ bias, int do_relu,
         const float* __restrict__ bng, const float* __restrict__ bnb) {
    __shared__ __align__(16) uint32_t As_hi[2][128][12];
    __shared__ __align__(16) uint32_t As_lo[2][128][12];
    __shared__ uint32_t Bs_hi[2][128][9];
    __shared__ uint32_t Bs_lo[2][128][9];
    __shared__ float s_sc[H2];
    __shared__ float s_sh[H2];

    int tid = threadIdx.x;
    int wid = tid >> 5, lane = tid & 31;
    int qid = lane >> 2, rid = lane & 3;
    int warp_m = wid & 1, warp_n = wid >> 1;
    int m0 = blockIdx.x * 128, n0 = blockIdx.y * 128;

    if (!PRESPLIT) {
        float inv = 1.f / (float)M;
        float mu = g_stats[tid] * inv;
        float var = g_stats[H2 + tid] * inv - mu * mu;
        float rs = rsqrtf(var + 1e-5f);
        float sc = bng[tid] * rs;
        s_sc[tid] = sc;
        s_sh[tid] = bnb[tid] - mu * sc;
        __syncthreads();
    }

    float acc[4][4][4];
#pragma unroll
    for (int i = 0; i < 4; i++)
#pragma unroll
        for (int j = 0; j < 4; j++)
#pragma unroll
            for (int q = 0; q < 4; q++) acc[i][j][q] = 0.f;

    // ldmatrix A base addresses (per-thread), buffer 0
    uint32_t sa_h = (uint32_t)__cvta_generic_to_shared(
        &As_hi[0][warp_m * 64 + (lane & 15)][(lane & 16) ? 4 : 0]);
    uint32_t sa_l = (uint32_t)__cvta_generic_to_shared(
        &As_lo[0][warp_m * 64 + (lane & 15)][(lane & 16) ? 4 : 0]);

    // ---- load assignments ----
    // presplit-A: 1 uint4 hi + 1 uint4 lo per thread per step
    int prow = tid >> 1;
    int phalf = (tid & 1) << 2;  // kpair offset 0 or 4
    bool pam = (m0 + prow) < M;
    // BN-A: 2 float4 per thread per step
    int arow0 = tid >> 2;
    int arow1 = arow0 + 64;
    int acg = (tid & 3) << 2;
    bool am0 = (m0 + arow0) < M;
    bool am1 = (m0 + arow1) < M;
    const float* Ap0 = Af + (size_t)(m0 + arow0) * lda + acg;
    const float* Ap1 = Af + (size_t)(m0 + arow1) * lda + acg;
    // B: warp kp, lane covers 4 n
    int kpw = wid;
    int ncB = lane << 2;
    const uint32_t* Bph = Bh + (size_t)kpw * ldbu + n0 + ncB;
    const uint32_t* Bpl = Bl + (size_t)kpw * ldbu + n0 + ncB;

    const uint4 z4u = make_uint4(0, 0, 0, 0);
    const float4 z4f = make_float4(0.f, 0.f, 0.f, 0.f);
    uint4 pah, pal, pbh, pbl;
    float4 ra0, ra1;

    // prologue prefetch (step 0)
    if (PRESPLIT) {
        const uint32_t* ah = Ah + (size_t)(m0 + prow) * lda + phalf;
        const uint32_t* al = Al + (size_t)(m0 + prow) * lda + phalf;
        pah = pam ? *(const uint4*)ah : z4u;
        pal = pam ? *(const uint4*)al : z4u;
    } else {
        ra0 = am0 ? *(const float4*)Ap0 : z4f;
        ra1 = am1 ? *(const float4*)Ap1 : z4f;
    }
    pbh = *(const uint4*)Bph;
    pbl = *(const uint4*)Bpl;

    int buf = 0;
    int nsteps = K >> 4;
    for (int s = 0; s < nsteps; s++) {
        // ---- stage current step ----
        if (PRESPLIT) {
            *(uint4*)&As_hi[buf][prow][phalf] = pah;
            *(uint4*)&As_lo[buf][prow][phalf] = pal;
        } else {
            int k0 = s << 4;
            float4 av = ra0;
            int gk = k0 + acg;
            av.x = fmaxf(fmaf(av.x, s_sc[gk + 0], s_sh[gk + 0]), 0.f);
            av.y = fmaxf(fmaf(av.y, s_sc[gk + 1], s_sh[gk + 1]), 0.f);
            av.z = fmaxf(fmaf(av.z, s_sc[gk + 2], s_sh[gk + 2]), 0.f);
            av.w = fmaxf(fmaf(av.w, s_sc[gk + 3], s_sh[gk + 3]), 0.f);
            if (!am0) { av.x = av.y = av.z = av.w = 0.f; }
            int kpa = acg >> 1;
            uint32_t h0, l0, h1, l1;
            splitpack(av.x, av.y, h0, l0);
            splitpack(av.z, av.w, h1, l1);
            As_hi[buf][arow0][kpa] = h0;     As_lo[buf][arow0][kpa] = l0;
            As_hi[buf][arow0][kpa + 1] = h1; As_lo[buf][arow0][kpa + 1] = l1;

            av = ra1;
            av.x = fmaxf(fmaf(av.x, s_sc[gk + 0], s_sh[gk + 0]), 0.f);
            av.y = fmaxf(fmaf(av.y, s_sc[gk + 1], s_sh[gk + 1]), 0.f);
            av.z = fmaxf(fmaf(av.z, s_sc[gk + 2], s_sh[gk + 2]), 0.f);
            av.w = fmaxf(fmaf(av.w, s_sc[gk + 3], s_sh[gk + 3]), 0.f);
            if (!am1) { av.x = av.y = av.z = av.w = 0.f; }
            splitpack(av.x, av.y, h0, l0);
            splitpack(av.z, av.w, h1, l1);
            As_hi[buf][arow1][kpa] = h0;     As_lo[buf][arow1][kpa] = l0;
            As_hi[buf][arow1][kpa + 1] = h1; As_lo[buf][arow1][kpa + 1] = l1;
        }
        Bs_hi[buf][ncB + 0][kpw] = pbh.x;
        Bs_hi[buf][ncB + 1][kpw] = pbh.y;
        Bs_hi[buf][ncB + 2][kpw] = pbh.z;
        Bs_hi[buf][ncB + 3][kpw] = pbh.w;
        Bs_lo[buf][ncB + 0][kpw] = pbl.x;
        Bs_lo[buf][ncB + 1][kpw] = pbl.y;
        Bs_lo[buf][ncB + 2][kpw] = pbl.z;
        Bs_lo[buf][ncB + 3][kpw] = pbl.w;
        __syncthreads();

        // ---- prefetch next step ----
        if (s + 1 < nsteps) {
            if (PRESPLIT) {
                const uint32_t* ah = Ah + (size_t)(m0 + prow) * lda + (s + 1) * 8 + phalf;
                const uint32_t* al = Al + (size_t)(m0 + prow) * lda + (s + 1) * 8 + phalf;
                pah = pam ? *(const uint4*)ah : z4u;
                pal = pam ? *(const uint4*)al : z4u;
            } else {
                int kn = (s + 1) << 4;
                ra0 = am0 ? *(const float4*)(Ap0 + kn) : z4f;
                ra1 = am1 ? *(const float4*)(Ap1 + kn) : z4f;
            }
            pbh = *(const uint4*)(Bph + (size_t)(s + 1) * 8 * ldbu);
            pbl = *(const uint4*)(Bpl + (size_t)(s + 1) * 8 * ldbu);
        }

        // ---- compute from smem[buf] ----
        uint32_t bfh[4][2], bfl[4][2];
#pragma unroll
        for (int nt = 0; nt < 4; nt++) {
            int nb = warp_n * 32 + nt * 8 + qid;
            bfh[nt][0] = Bs_hi[buf][nb][rid];     bfh[nt][1] = Bs_hi[buf][nb][rid + 4];
            bfl[nt][0] = Bs_lo[buf][nb][rid];     bfl[nt][1] = Bs_lo[buf][nb][rid + 4];
        }
        uint32_t abase_h = sa_h + buf * ABUF;
        uint32_t abase_l = sa_l + buf * ABUF;
#pragma unroll
        for (int mt = 0; mt < 4; mt++) {
            uint32_t ah[4], al[4];
            ldsm4(ah[0], ah[1], ah[2], ah[3], abase_h + mt * 768);
            ldsm4(al[0], al[1], al[2], al[3], abase_l + mt * 768);
#pragma unroll
            for (int nt = 0; nt < 4; nt++) {
                mma16(acc[mt][nt], ah, bfh[nt]);
                mma16(acc[mt][nt], ah, bfl[nt]);
                mma16(acc[mt][nt], al, bfh[nt]);
            }
        }
        buf ^= 1;
    }

    int m_base = m0 + warp_m * 64;
    int n_base = n0 + warp_n * 32;

#pragma unroll
    for (int mt = 0; mt < 4; mt++) {
        int r0g = m_base + mt * 16 + qid;
        int r1g = r0g + 8;
#pragma unroll
        for (int nt = 0; nt < 4; nt++) {
            int cg = n_base + nt * 8 + rid * 2;
            float v0 = acc[mt][nt][0], v1 = acc[mt][nt][1];
            float v2 = acc[mt][nt][2], v3 = acc[mt][nt][3];
            if (HAS_EPI) {
                float b0v = bias[cg], b1v = bias[cg + 1];
                v0 += b0v; v1 += b1v; v2 += b0v; v3 += b1v;
                if (do_relu) {
                    v0 = fmaxf(v0, 0.f); v1 = fmaxf(v1, 0.f);
                    v2 = fmaxf(v2, 0.f); v3 = fmaxf(v3, 0.f);
                }
            }
            if (r0g < M) *(float2*)(C + (size_t)r0g * ldc + cg) = make_float2(v0, v1);
            if (r1g < M) *(float2*)(C + (size_t)r1g * ldc + cg) = make_float2(v2, v3);
        }
    }

    if (COLSTATS) {
#pragma unroll
        for (int nt = 0; nt < 4; nt++) {
            float s0 = 0.f, q0 = 0.f, s1 = 0.f, q1 = 0.f;
#pragma unroll
            for (int mt = 0; mt < 4; mt++) {
                int r0g = m_base + mt * 16 + qid;
                const float* c = acc[mt][nt];
                if (r0g < M)     { s0 += c[0]; q0 += c[0] * c[0]; s1 += c[1]; q1 += c[1] * c[1]; }
                if (r0g + 8 < M) { s0 += c[2]; q0 += c[2] * c[2]; s1 += c[3]; q1 += c[3] * c[3]; }
            }
#pragma unroll
            for (int o = 4; o < 32; o <<= 1) {
                s0 += __shfl_xor_sync(0xffffffff, s0, o);
                q0 += __shfl_xor_sync(0xffffffff, q0, o);
                s1 += __shfl_xor_sync(0xffffffff, s1, o);
                q1 += __shfl_xor_sync(0xffffffff, q1, o);
            }
            if (lane < 4) {
                int cg = n_base + nt * 8 + lane * 2;
                atomicAdd(&g_stats[cg], s0);
                atomicAdd(&g_stats[H2 + cg], q0);
                atomicAdd(&g_stats[cg + 1], s1);
                atomicAdd(&g_stats[H2 + cg + 1], q1);
            }
        }
    }
}

// ---------------- SpMM: Aext[:,0:128] = (A + I) @ h, write split kpairs ----------------
__global__ void k_spmm(int n) {
    int wid = (blockIdx.x * blockDim.x + threadIdx.x) >> 5;
    int lane = threadIdx.x & 31;
    if (wid >= n) return;
    const float4* h4 = (const float4*)g_h;
    float4 acc = h4[(size_t)wid * 32 + lane];   // self loop
    int e0 = g_rowptr[wid], e1 = g_rowptr[wid + 1];
    for (int e = e0; e < e1; e++) {
        int c = g_colidx[e];
        float4 hv = h4[(size_t)c * 32 + lane];
        acc.x += hv.x; acc.y += hv.y; acc.z += hv.z; acc.w += hv.w;
    }
    uint32_t h0, l0, h1, l1;
    splitpack(acc.x, acc.y, h0, l0);
    splitpack(acc.z, acc.w, h1, l1);
    size_t base = (size_t)wid * KAP + 2 * lane;
    *(uint2*)&g_Aexth[base] = make_uint2(h0, h1);
    *(uint2*)&g_Aextl[base] = make_uint2(l0, l1);
}

// ---------------- fused head ----------------
__global__ void k_head(const int* __restrict__ batch, const float* __restrict__ disc_w, int n) {
    __shared__ float srow[H];
    int g = blockIdx.x;
    int c = threadIdx.x;
    int lo = 0, hi = n;
    while (lo < hi) { int m = (lo + hi) >> 1; if (batch[m] < g) lo = m + 1; else hi = m; }
    int lo2 = lo, hi2 = n;
    while (lo2 < hi2) { int m = (lo2 + hi2) >> 1; if (batch[m] < g + 1) lo2 = m + 1; else hi2 = m; }
    float s = 0.f;
    for (int r = lo; r < lo2; r++) s += g_h[(size_t)r * H + c];
    float cnt = fmaxf((float)(lo2 - lo), 1.f);
    float sm = 1.f / (1.f + expf(-s / cnt));
    srow[c] = sm;
    __syncthreads();
    float acc = 0.f;
    for (int k = 0; k < H; k++) acc = fmaf(srow[k], disc_w[k * H + c], acc);
    g_s2[g * H + c] = acc;
}

__global__ void k_out(const int* __restrict__ batch, float* __restrict__ out, int n) {
    int wid = (blockIdx.x * blockDim.x + threadIdx.x) >> 5;
    int lane = threadIdx.x & 31;
    if (wid >= n) return;
    int g = batch[wid];
    int g2 = (g + 1) % GG;
    const float4* h4 = (const float4*)g_h;
    const float4* s4 = (const float4*)g_s2;
    float4 hv = h4[(size_t)wid * 32 + lane];
    float4 av = s4[(size_t)g * 32 + lane];
    float4 bv = s4[(size_t)g2 * 32 + lane];
    float p = hv.x * av.x + hv.y * av.y + hv.z * av.z + hv.w * av.w;
    float q = hv.x * bv.x + hv.y * bv.y + hv.z * bv.z + hv.w * bv.w;
#pragma unroll
    for (int off = 16; off > 0; off >>= 1) {
        p += __shfl_xor_sync(0xffffffff, p, off);
        q += __shfl_xor_sync(0xffffffff, q, off);
    }
    if (lane == 0) { out[wid] = p; out[n + wid] = q; }
}

// ---------------- host ----------------
extern "C" void kernel_launch(void* const* d_in, const int* in_sizes, int n_in,
                              void* d_out, int out_size) {
    const int*   x_ids     = (const int*)d_in[0];
    const int*   ei        = (const int*)d_in[1];
    const int*   batch     = (const int*)d_in[2];
    const float* edge_attr = (const float*)d_in[3];
    const float* node_emb  = (const float*)d_in[4];
    const float* enc_w     = (const float*)d_in[5];
    const float* enc_b     = (const float*)d_in[6];
    const float* w1        = (const float*)d_in[7];
    const float* b1        = (const float*)d_in[8];
    const float* bn_g      = (const float*)d_in[9];
    const float* bn_b      = (const float*)d_in[10];
    const float* w2        = (const float*)d_in[11];
    const float* b2        = (const float*)d_in[12];
    const float* disc_w    = (const float*)d_in[13];
    float* out = (float*)d_out;

    int n  = in_sizes[0];
    int ec = in_sizes[1] / 2;
    const int* src = ei;
    const int* dst = ei + ec;

    float *p_z, *p_h;
    uint32_t *p_A0h, *p_A0l, *p_Aexth, *p_Aextl;
    uint32_t *p_W0ph, *p_W0pl, *p_W1ph, *p_W1pl, *p_W2h, *p_W2l;
    cudaGetSymbolAddress((void**)&p_z,     g_z);
    cudaGetSymbolAddress((void**)&p_h,     g_h);
    cudaGetSymbolAddress((void**)&p_A0h,   g_A0h);
    cudaGetSymbolAddress((void**)&p_A0l,   g_A0l);
    cudaGetSymbolAddress((void**)&p_Aexth, g_Aexth);
    cudaGetSymbolAddress((void**)&p_Aextl, g_Aextl);
    cudaGetSymbolAddress((void**)&p_W0ph,  g_W0ph);
    cudaGetSymbolAddress((void**)&p_W0pl,  g_W0pl);
    cudaGetSymbolAddress((void**)&p_W1ph,  g_W1ph);
    cudaGetSymbolAddress((void**)&p_W1pl,  g_W1pl);
    cudaGetSymbolAddress((void**)&p_W2h,   g_W2h);
    cudaGetSymbolAddress((void**)&p_W2l,   g_W2l);

    int eb    = (ec + 255) / 256;
    int nb    = (n + 255) / 256;
    int nb512 = (n + 511) / 512;
    int mb    = (n + 127) / 128;
    int warpsB = (n * 32 + 255) / 256;

    // --- graph structure + per-node features ---
    k_zero_deg<<<nb, 256>>>(n);
    k_count<<<eb, 256>>>(src, ec);
    k_scan1<<<nb512, 512>>>(n);
    k_scan2<<<1, 128>>>(nb512, n);
    k_scan3<<<nb, 256>>>(n);
    k_fill<<<eb, 256>>>(src, dst, ec);
    k_node<<<warpsB, 256>>>(x_ids, edge_attr, n);
    k_w2prep<<<128, 256>>>(w2);

    // --- layer 0 ---
    k_w0prep<<<8, 256>>>(node_emb, enc_w, enc_b, w1, b1);
    mma_gemm<true, false, true><<<dim3(mb, 2), 256>>>(
        p_A0h, p_A0l, nullptr, K0P, p_W0ph, p_W0pl, H2,
        p_z, H2, n, K0W, nullptr, 0, nullptr, nullptr);
    mma_gemm<false, true, false><<<dim3(mb, 1), 256>>>(
        nullptr, nullptr, p_z, H2, p_W2h, p_W2l, H,
        p_h, H, n, H2, b2, 1, bn_g, bn_b);

    // --- layer 1 ---
    k_w1prep<<<72, 256>>>(enc_w, enc_b, w1, b1);
    k_spmm<<<warpsB, 256>>>(n);
    mma_gemm<true, false, true><<<dim3(mb, 2), 256>>>(
        p_Aexth, p_Aextl, nullptr, KAP, p_W1ph, p_W1pl, H2,
        p_z, H2, n, KA, nullptr, 0, nullptr, nullptr);
    mma_gemm<false, true, false><<<dim3(mb, 1), 256>>>(
        nullptr, nullptr, p_z, H2, p_W2h + 128 * H, p_W2l + 128 * H, H,
        p_h, H, n, H2, b2 + H, 0, bn_g + H2, bn_b + H2);

    // --- head ---
    k_head<<<GG, H>>>(batch, disc_w, n);
    k_out<<<warpsB, 256>>>(batch, out, n);
}